// round 2
// baseline (speedup 1.0000x reference)
#include <cuda_runtime.h>
#include <math.h>

#define NN 1024
#define BB 128
#define DT 0.1f
#define STEPS 10

#define TI 32
#define TB 32
#define TJ 32

// Scratch (no cudaMalloc allowed)
__device__ float g_theta[BB * NN];
__device__ float g_sin[BB * NN];
__device__ float g_cos[BB * NN];

// -------------------------------------------------------------------------
// sin/cos of current theta (theta_init on step 0, g_theta afterwards)
// -------------------------------------------------------------------------
__global__ void sincos_kernel(const float* __restrict__ theta_init, int use_init) {
    int idx = blockIdx.x * blockDim.x + threadIdx.x;
    if (idx >= BB * NN) return;
    float t = use_init ? theta_init[idx] : g_theta[idx];
    float s, c;
    sincosf(t, &s, &c);
    g_sin[idx] = s;
    g_cos[idx] = c;
}

// -------------------------------------------------------------------------
// One Euler step:
//   S[b,i] = sum_j K[i,j] * sin(theta[b,j])
//   C[b,i] = sum_j K[i,j] * cos(theta[b,j])
//   coupling = cos(theta[b,i])*S - sin(theta[b,i])*C
//   theta'   = wrap(theta + DT*(omega + Kg/N * coupling))
// Tiled shared-memory dual-GEMM. Block = 16x16 threads, 2x2 register tile,
// covers a 32(i) x 32(b) output tile. Grid = (N/32, B/32) = (32, 4).
// -------------------------------------------------------------------------
__global__ void update_kernel(const float* __restrict__ theta_init, int use_init,
                              const float* __restrict__ Kmat,
                              const float* __restrict__ omega,
                              const float* __restrict__ Kg) {
    __shared__ float sK[TI][TJ + 1];
    __shared__ float sS[TB][TJ + 1];
    __shared__ float sC[TB][TJ + 1];

    const float* __restrict__ theta_in = use_init ? theta_init : g_theta;

    int tx = threadIdx.x;               // 0..15, batch direction
    int ty = threadIdx.y;               // 0..15, oscillator direction
    int tid = ty * 16 + tx;

    int iBase = blockIdx.x * TI;
    int bBase = blockIdx.y * TB;

    float accS[2][2] = {{0.f, 0.f}, {0.f, 0.f}};  // [ii][bb]
    float accC[2][2] = {{0.f, 0.f}, {0.f, 0.f}};

    for (int j0 = 0; j0 < NN; j0 += TJ) {
        // Load 32x32 tiles; 256 threads x 4 elems, coalesced along j.
        #pragma unroll
        for (int k = 0; k < 4; k++) {
            int e = tid + k * 256;      // 0..1023
            int r = e >> 5;
            int c = e & 31;
            sK[r][c] = Kmat[(iBase + r) * NN + j0 + c];
            sS[r][c] = g_sin[(bBase + r) * NN + j0 + c];
            sC[r][c] = g_cos[(bBase + r) * NN + j0 + c];
        }
        __syncthreads();

        #pragma unroll
        for (int jj = 0; jj < TJ; jj++) {
            float k0 = sK[2 * ty + 0][jj];
            float k1 = sK[2 * ty + 1][jj];
            float s0 = sS[2 * tx + 0][jj];
            float s1 = sS[2 * tx + 1][jj];
            float c0 = sC[2 * tx + 0][jj];
            float c1 = sC[2 * tx + 1][jj];
            accS[0][0] = fmaf(k0, s0, accS[0][0]);
            accS[0][1] = fmaf(k0, s1, accS[0][1]);
            accS[1][0] = fmaf(k1, s0, accS[1][0]);
            accS[1][1] = fmaf(k1, s1, accS[1][1]);
            accC[0][0] = fmaf(k0, c0, accC[0][0]);
            accC[0][1] = fmaf(k0, c1, accC[0][1]);
            accC[1][0] = fmaf(k1, c0, accC[1][0]);
            accC[1][1] = fmaf(k1, c1, accC[1][1]);
        }
        __syncthreads();
    }

    float kg_n = Kg[0] / (float)NN;

    #pragma unroll
    for (int ii = 0; ii < 2; ii++) {
        int i = iBase + 2 * ty + ii;
        float om = omega[i];
        #pragma unroll
        for (int bb = 0; bb < 2; bb++) {
            int b = bBase + 2 * tx + bb;
            int idx = b * NN + i;
            float ci = g_cos[idx];
            float si = g_sin[idx];
            float coupling = ci * accS[ii][bb] - si * accC[ii][bb];
            float t = theta_in[idx] + DT * (om + kg_n * coupling);
            // wrap to (-pi, pi] exactly like reference: atan2(sin t, cos t)
            float s, c;
            sincosf(t, &s, &c);
            g_theta[idx] = atan2f(s, c);
        }
    }
}

// -------------------------------------------------------------------------
// Final: copy theta to out[0 : B*N], coherence per batch to out[B*N : B*N+B]
// One block per batch.
// -------------------------------------------------------------------------
__global__ void finalize_kernel(float* __restrict__ out) {
    int b = blockIdx.x;
    int t = threadIdx.x;

    __shared__ float rc[256];
    __shared__ float rs[256];

    float sumc = 0.f, sums = 0.f;
    for (int j = t; j < NN; j += 256) {
        float th = g_theta[b * NN + j];
        float s, c;
        sincosf(th, &s, &c);
        sumc += c;
        sums += s;
        out[b * NN + j] = th;
    }
    rc[t] = sumc;
    rs[t] = sums;
    __syncthreads();
    for (int off = 128; off > 0; off >>= 1) {
        if (t < off) {
            rc[t] += rc[t + off];
            rs[t] += rs[t + off];
        }
        __syncthreads();
    }
    if (t == 0) {
        float cm = rc[0] / (float)NN;
        float sm = rs[0] / (float)NN;
        out[BB * NN + b] = sqrtf(cm * cm + sm * sm);
    }
}

// -------------------------------------------------------------------------
extern "C" void kernel_launch(void* const* d_in, const int* in_sizes, int n_in,
                              void* d_out, int out_size) {
    const float* theta_init = (const float*)d_in[0];   // [B, N]
    const float* Kmat       = (const float*)d_in[1];   // [N, N]
    const float* omega      = (const float*)d_in[2];   // [N]
    const float* Kg         = (const float*)d_in[3];   // scalar
    float* out = (float*)d_out;

    dim3 ublock(16, 16);
    dim3 ugrid(NN / TI, BB / TB);
    int sc_blocks = (BB * NN + 255) / 256;

    for (int s = 0; s < STEPS; s++) {
        int use_init = (s == 0) ? 1 : 0;
        sincos_kernel<<<sc_blocks, 256>>>(theta_init, use_init);
        update_kernel<<<ugrid, ublock>>>(theta_init, use_init, Kmat, omega, Kg);
    }
    finalize_kernel<<<BB, 256>>>(out);
}

// round 3
// speedup vs baseline: 1.5217x; 1.5217x over previous
#include <cuda_runtime.h>
#include <math.h>

#define NN 1024
#define BB 128
#define DT 0.1f
#define STEPS 10
#define JCH 8              // split-K chunks
#define JC  (NN / JCH)     // 128 j per chunk

typedef unsigned long long ull;

// ---- scratch (__device__ globals; no cudaMalloc allowed) -----------------
__device__ float  g_theta[NN * BB];          // wrapped theta, [i][b] layout
__device__ float2 g_scT[NN * BB];            // (sin,cos) of theta, [i][b]
__device__ float2 g_part[JCH * NN * BB];     // split-K partials (S,C), [chunk][i][b]

// packed f32x2 fused multiply-add: d = a*b + c elementwise on two packed f32
__device__ __forceinline__ ull ffma2(ull a, ull b, ull c) {
    ull d;
    asm("fma.rn.f32x2 %0, %1, %2, %3;" : "=l"(d) : "l"(a), "l"(b), "l"(c));
    return d;
}

// ---------------------------------------------------------------------------
// init: transpose theta_init [b][i] -> [i][b], compute sincos
// ---------------------------------------------------------------------------
__global__ void init_kernel(const float* __restrict__ theta_init) {
    int idx = blockIdx.x * blockDim.x + threadIdx.x;   // idx = i*BB + b
    if (idx >= NN * BB) return;
    int i = idx >> 7;
    int b = idx & (BB - 1);
    float t = theta_init[b * NN + i];
    g_theta[idx] = t;
    float s, c;
    sincosf(t, &s, &c);
    g_scT[idx] = make_float2(s, c);
}

// ---------------------------------------------------------------------------
// split-K dual GEMM via packed f32x2:
//   part[ch][i][b] = ( sum_j K[i,j]*sin[j,b] , sum_j K[i,j]*cos[j,b] )  over j-chunk ch
// block = 8(tx,b) x 8(ty,i) = 64 threads; per-thread 4i x 4b tile of f32x2 (S,C) accs.
// grid = (32 i-tiles, 4 b-tiles, JCH chunks) = 1024 blocks.
// ---------------------------------------------------------------------------
__global__ __launch_bounds__(64) void gemm_kernel(const float* __restrict__ Kmat) {
    __shared__ float2 sK2[32][33];   // (k,k) pre-splatted, pad -> conflict-free
    __shared__ float2 sSC[32][32];   // (sin,cos) tile, [jj][b]

    const int tx = threadIdx.x;           // 0..7  (b)
    const int ty = threadIdx.y;           // 0..7  (i)
    const int tid = ty * 8 + tx;
    const int iBase = blockIdx.x * 32;
    const int bBase = blockIdx.y * 32;
    const int j0 = blockIdx.z * JC;

    ull acc[4][4];
    #pragma unroll
    for (int ii = 0; ii < 4; ii++)
        #pragma unroll
        for (int bb = 0; bb < 4; bb++) acc[ii][bb] = 0ull;

    for (int js = 0; js < JC; js += 32) {
        const int jg = j0 + js;
        // K tile 32i x 32j, pre-splatted to (k,k)
        #pragma unroll
        for (int k = 0; k < 16; k++) {
            int e = tid + k * 64;
            int r = e >> 5, c = e & 31;
            float kv = Kmat[(iBase + r) * NN + jg + c];
            sK2[r][c] = make_float2(kv, kv);
        }
        // SC tile 32j x 32b (coalesced float2 loads: consecutive tid -> consecutive b)
        #pragma unroll
        for (int k = 0; k < 16; k++) {
            int e = tid + k * 64;
            int b = e & 31, jj = e >> 5;
            sSC[jj][b] = g_scT[(jg + jj) * BB + bBase + b];
        }
        __syncthreads();

        #pragma unroll 8
        for (int jj = 0; jj < 32; jj++) {
            ull kv[4];
            #pragma unroll
            for (int ii = 0; ii < 4; ii++)
                kv[ii] = *reinterpret_cast<const ull*>(&sK2[ty * 4 + ii][jj]);
            ulonglong2 scA = *reinterpret_cast<const ulonglong2*>(&sSC[jj][tx * 4]);
            ulonglong2 scB = *reinterpret_cast<const ulonglong2*>(&sSC[jj][tx * 4 + 2]);
            ull sc[4] = {scA.x, scA.y, scB.x, scB.y};
            #pragma unroll
            for (int ii = 0; ii < 4; ii++)
                #pragma unroll
                for (int bb = 0; bb < 4; bb++)
                    acc[ii][bb] = ffma2(kv[ii], sc[bb], acc[ii][bb]);
        }
        __syncthreads();
    }

    // store partials: [chunk][i][b], 16B vector stores
    float2* P = g_part + (size_t)blockIdx.z * (NN * BB);
    #pragma unroll
    for (int ii = 0; ii < 4; ii++) {
        int i = iBase + ty * 4 + ii;
        ulonglong2* dst = reinterpret_cast<ulonglong2*>(&P[i * BB + bBase + tx * 4]);
        ulonglong2 v0; v0.x = acc[ii][0]; v0.y = acc[ii][1];
        ulonglong2 v1; v1.x = acc[ii][2]; v1.y = acc[ii][3];
        dst[0] = v0;
        dst[1] = v1;
    }
}

// ---------------------------------------------------------------------------
// epilogue: reduce split-K partials, Euler update, wrap, sincos for next step
// ---------------------------------------------------------------------------
__global__ void epilogue_kernel(const float* __restrict__ omega,
                                const float* __restrict__ Kg) {
    int idx = blockIdx.x * blockDim.x + threadIdx.x;   // i*BB + b
    if (idx >= NN * BB) return;

    float S = 0.f, C = 0.f;
    #pragma unroll
    for (int ch = 0; ch < JCH; ch++) {
        float2 p = g_part[(size_t)ch * (NN * BB) + idx];
        S += p.x;
        C += p.y;
    }
    int i = idx >> 7;
    float2 sc = g_scT[idx];                 // (sin, cos) of current theta
    float coupling = sc.y * S - sc.x * C;   // cos_i * Ssum - sin_i * Csum
    float kgn = Kg[0] * (1.0f / (float)NN);
    float t = g_theta[idx] + DT * (omega[i] + kgn * coupling);
    float s, c;
    sincosf(t, &s, &c);
    g_theta[idx] = atan2f(s, c);            // wrap to (-pi, pi] like reference
    g_scT[idx] = make_float2(s, c);         // sincos(wrapped) == sincos(t)
}

// ---------------------------------------------------------------------------
// finalize: theta -> out[0:B*N] (transposed back), coherence -> out[B*N:B*N+B]
// ---------------------------------------------------------------------------
__global__ void finalize_kernel(float* __restrict__ out) {
    int b = blockIdx.x;
    int t = threadIdx.x;

    __shared__ float rc[256];
    __shared__ float rs[256];

    float sumc = 0.f, sums = 0.f;
    for (int i = t; i < NN; i += 256) {
        int idx = i * BB + b;
        out[b * NN + i] = g_theta[idx];
        float2 sc = g_scT[idx];
        sums += sc.x;
        sumc += sc.y;
    }
    rc[t] = sumc;
    rs[t] = sums;
    __syncthreads();
    for (int off = 128; off > 0; off >>= 1) {
        if (t < off) {
            rc[t] += rc[t + off];
            rs[t] += rs[t + off];
        }
        __syncthreads();
    }
    if (t == 0) {
        float cm = rc[0] * (1.0f / (float)NN);
        float sm = rs[0] * (1.0f / (float)NN);
        out[BB * NN + b] = sqrtf(cm * cm + sm * sm);
    }
}

// ---------------------------------------------------------------------------
extern "C" void kernel_launch(void* const* d_in, const int* in_sizes, int n_in,
                              void* d_out, int out_size) {
    const float* theta_init = (const float*)d_in[0];   // [B, N]
    const float* Kmat       = (const float*)d_in[1];   // [N, N]
    const float* omega      = (const float*)d_in[2];   // [N]
    const float* Kg         = (const float*)d_in[3];   // scalar
    float* out = (float*)d_out;

    dim3 gblock(8, 8);
    dim3 ggrid(NN / 32, BB / 32, JCH);   // (32, 4, 8) = 1024 blocks

    init_kernel<<<(NN * BB + 255) / 256, 256>>>(theta_init);
    for (int s = 0; s < STEPS; s++) {
        gemm_kernel<<<ggrid, gblock>>>(Kmat);
        epilogue_kernel<<<(NN * BB + 255) / 256, 256>>>(omega, Kg);
    }
    finalize_kernel<<<BB, 256>>>(out);
}

// round 5
// speedup vs baseline: 3.6034x; 2.3680x over previous
#include <cuda_runtime.h>
#include <cuda_bf16.h>
#include <math.h>
#include <stdint.h>

#define NN 1024
#define BB 128
#define NT 256            // 2*BB interleaved sin/cos columns
#define DT 0.1f
#define STEPS 10

#define TM 64             // CTA tile M (i)
#define TN 32             // CTA tile N (interleaved cols) = 16 b's
#define BK 64             // K chunk
#define NCH (NN / BK)     // 16 chunks

// ---------------- scratch (__device__ globals; no cudaMalloc) --------------
__device__ __nv_bfloat16 g_Kb[NN * NN];        // K in bf16, row-major [i][j]
__device__ __nv_bfloat16 g_scB[2][NT * NN];    // ping-pong B operand: [n][j]
__device__ float         g_theta[NN * BB];     // wrapped theta, [i][b]

// ---------------- PTX helpers ----------------------------------------------
__device__ __forceinline__ uint32_t smem_u32(const void* p) {
    uint32_t a;
    asm("{ .reg .u64 t; cvta.to.shared.u64 t, %1; cvt.u32.u64 %0, t; }" : "=r"(a) : "l"(p));
    return a;
}
__device__ __forceinline__ void cp16(uint32_t dst, const void* src) {
    asm volatile("cp.async.cg.shared.global [%0], [%1], 16;" :: "r"(dst), "l"(src));
}
#define CP_COMMIT() asm volatile("cp.async.commit_group;" ::: "memory")
#define CP_WAIT0()  asm volatile("cp.async.wait_group 0;" ::: "memory")

__device__ __forceinline__ void ldm4(uint32_t& r0, uint32_t& r1, uint32_t& r2, uint32_t& r3,
                                     uint32_t addr) {
    asm volatile("ldmatrix.sync.aligned.m8n8.x4.shared.b16 {%0,%1,%2,%3}, [%4];"
                 : "=r"(r0), "=r"(r1), "=r"(r2), "=r"(r3) : "r"(addr));
}
__device__ __forceinline__ void mma_bf16(float* d, const uint32_t* a, uint32_t b0, uint32_t b1) {
    asm volatile(
        "mma.sync.aligned.m16n8k16.row.col.f32.bf16.bf16.f32 "
        "{%0,%1,%2,%3}, {%4,%5,%6,%7}, {%8,%9}, {%0,%1,%2,%3};"
        : "+f"(d[0]), "+f"(d[1]), "+f"(d[2]), "+f"(d[3])
        : "r"(a[0]), "r"(a[1]), "r"(a[2]), "r"(a[3]), "r"(b0), "r"(b1));
}

// ---------------------------------------------------------------------------
// init 1: K (f32) -> bf16
// ---------------------------------------------------------------------------
__global__ void convK_kernel(const float* __restrict__ Kmat) {
    int g = blockIdx.x * blockDim.x + threadIdx.x;
    if (g >= NN * NN / 4) return;
    float4 v = reinterpret_cast<const float4*>(Kmat)[g];
    __nv_bfloat162* d = reinterpret_cast<__nv_bfloat162*>(g_Kb) + g * 2;
    d[0] = __floats2bfloat162_rn(v.x, v.y);
    d[1] = __floats2bfloat162_rn(v.z, v.w);
}

// ---------------------------------------------------------------------------
// init 2: theta_init [b][i] -> g_theta [i][b]; B operand rows 2b / 2b+1
// ---------------------------------------------------------------------------
__global__ void init_theta_kernel(const float* __restrict__ theta_init) {
    int g = blockIdx.x * blockDim.x + threadIdx.x;     // g = b*NN + i
    if (g >= BB * NN) return;
    int b = g >> 10, i = g & (NN - 1);
    float t = theta_init[g];
    float s, c;
    sincosf(t, &s, &c);
    g_theta[i * BB + b] = t;
    g_scB[0][(2 * b) * NN + i]     = __float2bfloat16(s);
    g_scB[0][(2 * b + 1) * NN + i] = __float2bfloat16(c);
}

// ---------------------------------------------------------------------------
// fused step: D[i,n] = sum_j Kb[i,j] * scB[cur][n,j]  (bf16 HMMA, f32 acc)
// then per (i,b): coupling = cos_i*S - sin_i*C; Euler; wrap; emit scB[nxt].
// grid (16,8)=128 CTAs, 256 thr (8 warps: 4 m-warps x 2 n-warps, m16 x n16).
// ---------------------------------------------------------------------------
__global__ __launch_bounds__(256) void step_kernel(const float* __restrict__ omega,
                                                   const float* __restrict__ Kg,
                                                   int cur, int nxt) {
    __shared__ __nv_bfloat16 sA[2][TM * BK];   // swizzled, 8KB per buf
    __shared__ __nv_bfloat16 sB[2][TN * BK];   // swizzled, 4KB per buf

    const int t = threadIdx.x;
    const int lane = t & 31;
    const int wid = t >> 5;
    const int wm = wid & 3;                    // m-warp 0..3
    const int wn = wid >> 2;                   // n-warp 0..1
    const int i0 = blockIdx.x * TM;
    const int n0 = blockIdx.y * TN;

    const uint32_t sAu = smem_u32(sA);
    const uint32_t sBu = smem_u32(sB);
    const __nv_bfloat16* __restrict__ Bsrc = g_scB[cur];

    // ---- per-thread load indices (A: 2 chunks, B: 1 chunk of 16B) ----
    // A: e in [0,512): row r=e>>3 (0..63), chunk c=e&7. swizzle: c ^= (r&7)
    int ea0 = t, ea1 = t + 256;
    int ar0 = ea0 >> 3, ac0 = ea0 & 7;
    int ar1 = ea1 >> 3, ac1 = ea1 & 7;
    uint32_t adst0 = sAu + (uint32_t)(ar0 * 128 + ((ac0 ^ (ar0 & 7)) << 4));
    uint32_t adst1 = sAu + (uint32_t)(ar1 * 128 + ((ac1 ^ (ar1 & 7)) << 4));
    int br = t >> 3, bc = t & 7;               // B rows 0..31
    uint32_t bdst = sBu + (uint32_t)(br * 128 + ((bc ^ (br & 7)) << 4));

    const __nv_bfloat16* asrc0 = &g_Kb[(size_t)(i0 + ar0) * NN + ac0 * 8];
    const __nv_bfloat16* asrc1 = &g_Kb[(size_t)(i0 + ar1) * NN + ac1 * 8];
    const __nv_bfloat16* bsrc  = &Bsrc[(size_t)(n0 + br) * NN + bc * 8];

    // ---- ldmatrix lane addressing (row part fixed per lane) ----
    int sub = lane >> 3, lr = lane & 7;
    int arow = wm * 16 + ((sub & 1) << 3) + lr;          // A: m0-7/m8-15 pairs
    int acsel = sub >> 1;                                 // k half
    uint32_t aBase = sAu + (uint32_t)(arow * 128);
    int axor = (arow & 7);

    int brow = wn * 16 + ((sub >> 1) << 3) + lr;          // B: n0-7/n8-15
    int bcsel = sub & 1;                                  // k half
    uint32_t bBase = sBu + (uint32_t)(brow * 128);
    int bxor = (brow & 7);

    float acc0[4] = {0.f, 0.f, 0.f, 0.f};    // n8 block 0
    float acc1[4] = {0.f, 0.f, 0.f, 0.f};    // n8 block 1

    // ---- prologue: load chunk 0 into buf 0 ----
    cp16(adst0, asrc0);
    cp16(adst1, asrc1);
    cp16(bdst, bsrc);
    CP_COMMIT();

    for (int k = 0; k < NCH; k++) {
        CP_WAIT0();
        __syncthreads();
        int buf = k & 1;
        if (k + 1 < NCH) {
            int nb = (k + 1) & 1;
            size_t koff = (size_t)(k + 1) * BK;
            cp16(adst0 + nb * (TM * BK * 2), asrc0 + koff);
            cp16(adst1 + nb * (TM * BK * 2), asrc1 + koff);
            cp16(bdst + nb * (TN * BK * 2), bsrc + koff);
            CP_COMMIT();
        }
        uint32_t aB = aBase + (uint32_t)(buf * (TM * BK * 2));
        uint32_t bB = bBase + (uint32_t)(buf * (TN * BK * 2));
        #pragma unroll
        for (int ks = 0; ks < 4; ks++) {
            uint32_t a[4], b[4];
            int ach = ks * 2 + acsel;
            int bch = ks * 2 + bcsel;
            ldm4(a[0], a[1], a[2], a[3], aB + (uint32_t)((ach ^ axor) << 4));
            ldm4(b[0], b[1], b[2], b[3], bB + (uint32_t)((bch ^ bxor) << 4));
            mma_bf16(acc0, a, b[0], b[1]);
            mma_bf16(acc1, a, b[2], b[3]);
        }
        __syncthreads();
    }

    // ---- fused epilogue ----
    const float kgn = Kg[0] * (1.0f / (float)NN);
    const int tq = lane >> 2;        // fragment row within m8
    const int tr = lane & 3;         // fragment col pair
    __nv_bfloat16* __restrict__ Bn = g_scB[nxt];

    #pragma unroll
    for (int nb = 0; nb < 2; nb++) {
        const float* acc = nb ? acc1 : acc0;
        int n_even = n0 + wn * 16 + nb * 8 + tr * 2;   // even column = sin
        int b = n_even >> 1;
        #pragma unroll
        for (int half = 0; half < 2; half++) {
            int i = i0 + wm * 16 + half * 8 + tq;
            float S = acc[half * 2 + 0];
            float C = acc[half * 2 + 1];
            int idx = i * BB + b;
            float th = g_theta[idx];
            float si, ci;
            sincosf(th, &si, &ci);
            float coup = ci * S - si * C;
            float tn = th + DT * (omega[i] + kgn * coup);
            float s, c;
            sincosf(tn, &s, &c);
            g_theta[idx] = atan2f(s, c);               // wrap like reference
            Bn[(size_t)(2 * b) * NN + i]     = __float2bfloat16(s);
            Bn[(size_t)(2 * b + 1) * NN + i] = __float2bfloat16(c);
        }
    }
}

// ---------------------------------------------------------------------------
// finalize: theta -> out[0:B*N] (transposed), coherence -> out[B*N : +B]
// ---------------------------------------------------------------------------
__global__ void finalize_kernel(float* __restrict__ out) {
    int b = blockIdx.x;
    int t = threadIdx.x;
    __shared__ float rc[256], rs[256];

    float sumc = 0.f, sums = 0.f;
    for (int i = t; i < NN; i += 256) {
        float th = g_theta[i * BB + b];
        out[b * NN + i] = th;
        float s, c;
        sincosf(th, &s, &c);
        sums += s;
        sumc += c;
    }
    rc[t] = sumc; rs[t] = sums;
    __syncthreads();
    for (int off = 128; off > 0; off >>= 1) {
        if (t < off) { rc[t] += rc[t + off]; rs[t] += rs[t + off]; }
        __syncthreads();
    }
    if (t == 0) {
        float cm = rc[0] * (1.0f / (float)NN);
        float sm = rs[0] * (1.0f / (float)NN);
        out[BB * NN + b] = sqrtf(cm * cm + sm * sm);
    }
}

// ---------------------------------------------------------------------------
extern "C" void kernel_launch(void* const* d_in, const int* in_sizes, int n_in,
                              void* d_out, int out_size) {
    const float* theta_init = (const float*)d_in[0];
    const float* Kmat       = (const float*)d_in[1];
    const float* omega      = (const float*)d_in[2];
    const float* Kg         = (const float*)d_in[3];
    float* out = (float*)d_out;

    convK_kernel<<<NN * NN / 4 / 256, 256>>>(Kmat);
    init_theta_kernel<<<BB * NN / 256, 256>>>(theta_init);

    dim3 ggrid(NN / TM, NT / TN);   // (16, 8) = 128 CTAs
    for (int s = 0; s < STEPS; s++) {
        step_kernel<<<ggrid, 256>>>(omega, Kg, s & 1, (s + 1) & 1);
    }
    finalize_kernel<<<BB, 256>>>(out);
}

// round 6
// speedup vs baseline: 3.6686x; 1.0181x over previous
#include <cuda_runtime.h>
#include <cuda_bf16.h>
#include <math.h>
#include <stdint.h>

#define NN 1024
#define BB 128
#define NT 256            // 2*BB interleaved sin/cos columns
#define DT 0.1f
#define STEPS 10

#define TM 64             // CTA tile M (i)
#define TN 32             // CTA tile N (interleaved cols) = 16 b's
#define BK 64             // K chunk
#define NCH (NN / BK)     // 16 chunks

// ---------------- scratch (__device__ globals; no cudaMalloc) --------------
__device__ __nv_bfloat16 g_Kb[NN * NN];        // K in bf16, row-major [i][j]
__device__ __nv_bfloat16 g_scB[2][NT * NN];    // ping-pong B operand: [n][j]
__device__ float         g_theta[NN * BB];     // wrapped theta, [i][b]

// ---------------- PTX helpers ----------------------------------------------
__device__ __forceinline__ uint32_t smem_u32(const void* p) {
    uint32_t a;
    asm("{ .reg .u64 t; cvta.to.shared.u64 t, %1; cvt.u32.u64 %0, t; }" : "=r"(a) : "l"(p));
    return a;
}
__device__ __forceinline__ void cp16(uint32_t dst, const void* src) {
    asm volatile("cp.async.cg.shared.global [%0], [%1], 16;" :: "r"(dst), "l"(src));
}
#define CP_COMMIT() asm volatile("cp.async.commit_group;" ::: "memory")
#define CP_WAIT0()  asm volatile("cp.async.wait_group 0;" ::: "memory")

__device__ __forceinline__ void ldm4(uint32_t& r0, uint32_t& r1, uint32_t& r2, uint32_t& r3,
                                     uint32_t addr) {
    asm volatile("ldmatrix.sync.aligned.m8n8.x4.shared.b16 {%0,%1,%2,%3}, [%4];"
                 : "=r"(r0), "=r"(r1), "=r"(r2), "=r"(r3) : "r"(addr));
}
__device__ __forceinline__ void mma_bf16(float* d, const uint32_t* a, uint32_t b0, uint32_t b1) {
    asm volatile(
        "mma.sync.aligned.m16n8k16.row.col.f32.bf16.bf16.f32 "
        "{%0,%1,%2,%3}, {%4,%5,%6,%7}, {%8,%9}, {%0,%1,%2,%3};"
        : "+f"(d[0]), "+f"(d[1]), "+f"(d[2]), "+f"(d[3])
        : "r"(a[0]), "r"(a[1]), "r"(a[2]), "r"(a[3]), "r"(b0), "r"(b1));
}

// ---------------------------------------------------------------------------
// init 1: K (f32) -> bf16
// ---------------------------------------------------------------------------
__global__ void convK_kernel(const float* __restrict__ Kmat) {
    int g = blockIdx.x * blockDim.x + threadIdx.x;
    if (g >= NN * NN / 4) return;
    float4 v = reinterpret_cast<const float4*>(Kmat)[g];
    __nv_bfloat162* d = reinterpret_cast<__nv_bfloat162*>(g_Kb) + g * 2;
    d[0] = __floats2bfloat162_rn(v.x, v.y);
    d[1] = __floats2bfloat162_rn(v.z, v.w);
}

// ---------------------------------------------------------------------------
// init 2: theta_init [b][i] -> g_theta [i][b]; B operand rows 2b / 2b+1
// ---------------------------------------------------------------------------
__global__ void init_theta_kernel(const float* __restrict__ theta_init) {
    int g = blockIdx.x * blockDim.x + threadIdx.x;     // g = b*NN + i
    if (g >= BB * NN) return;
    int b = g >> 10, i = g & (NN - 1);
    float t = theta_init[g];
    float s, c;
    sincosf(t, &s, &c);
    g_theta[i * BB + b] = t;
    g_scB[0][(2 * b) * NN + i]     = __float2bfloat16(s);
    g_scB[0][(2 * b + 1) * NN + i] = __float2bfloat16(c);
}

// ---------------------------------------------------------------------------
// fused step: D[i,n] = sum_j Kb[i,j] * scB[cur][n,j]  (bf16 HMMA, f32 acc)
// then per (i,b): coupling = cos_i*S - sin_i*C; Euler; wrap; emit scB[nxt].
// grid (16,8)=128 CTAs, 256 thr (8 warps: 4 m-warps x 2 n-warps, m16 x n16).
// ---------------------------------------------------------------------------
__global__ __launch_bounds__(256) void step_kernel(const float* __restrict__ omega,
                                                   const float* __restrict__ Kg,
                                                   int cur, int nxt) {
    __shared__ __nv_bfloat16 sA[2][TM * BK];   // swizzled, 8KB per buf
    __shared__ __nv_bfloat16 sB[2][TN * BK];   // swizzled, 4KB per buf

    const int t = threadIdx.x;
    const int lane = t & 31;
    const int wid = t >> 5;
    const int wm = wid & 3;                    // m-warp 0..3
    const int wn = wid >> 2;                   // n-warp 0..1
    const int i0 = blockIdx.x * TM;
    const int n0 = blockIdx.y * TN;

    const uint32_t sAu = smem_u32(sA);
    const uint32_t sBu = smem_u32(sB);
    const __nv_bfloat16* __restrict__ Bsrc = g_scB[cur];

    // ---- per-thread load indices (A: 2 chunks, B: 1 chunk of 16B) ----
    // A: e in [0,512): row r=e>>3 (0..63), chunk c=e&7. swizzle: c ^= (r&7)
    int ea0 = t, ea1 = t + 256;
    int ar0 = ea0 >> 3, ac0 = ea0 & 7;
    int ar1 = ea1 >> 3, ac1 = ea1 & 7;
    uint32_t adst0 = sAu + (uint32_t)(ar0 * 128 + ((ac0 ^ (ar0 & 7)) << 4));
    uint32_t adst1 = sAu + (uint32_t)(ar1 * 128 + ((ac1 ^ (ar1 & 7)) << 4));
    int br = t >> 3, bc = t & 7;               // B rows 0..31
    uint32_t bdst = sBu + (uint32_t)(br * 128 + ((bc ^ (br & 7)) << 4));

    const __nv_bfloat16* asrc0 = &g_Kb[(size_t)(i0 + ar0) * NN + ac0 * 8];
    const __nv_bfloat16* asrc1 = &g_Kb[(size_t)(i0 + ar1) * NN + ac1 * 8];
    const __nv_bfloat16* bsrc  = &Bsrc[(size_t)(n0 + br) * NN + bc * 8];

    // ---- ldmatrix lane addressing (row part fixed per lane) ----
    int sub = lane >> 3, lr = lane & 7;
    int arow = wm * 16 + ((sub & 1) << 3) + lr;          // A: m0-7/m8-15 pairs
    int acsel = sub >> 1;                                 // k half
    uint32_t aBase = sAu + (uint32_t)(arow * 128);
    int axor = (arow & 7);

    int brow = wn * 16 + ((sub >> 1) << 3) + lr;          // B: n0-7/n8-15
    int bcsel = sub & 1;                                  // k half
    uint32_t bBase = sBu + (uint32_t)(brow * 128);
    int bxor = (brow & 7);

    float acc0[4] = {0.f, 0.f, 0.f, 0.f};    // n8 block 0
    float acc1[4] = {0.f, 0.f, 0.f, 0.f};    // n8 block 1

    // ---- prologue: load chunk 0 into buf 0 ----
    cp16(adst0, asrc0);
    cp16(adst1, asrc1);
    cp16(bdst, bsrc);
    CP_COMMIT();

    for (int k = 0; k < NCH; k++) {
        CP_WAIT0();
        __syncthreads();
        int buf = k & 1;
        if (k + 1 < NCH) {
            int nb = (k + 1) & 1;
            size_t koff = (size_t)(k + 1) * BK;
            cp16(adst0 + nb * (TM * BK * 2), asrc0 + koff);
            cp16(adst1 + nb * (TM * BK * 2), asrc1 + koff);
            cp16(bdst + nb * (TN * BK * 2), bsrc + koff);
            CP_COMMIT();
        }
        uint32_t aB = aBase + (uint32_t)(buf * (TM * BK * 2));
        uint32_t bB = bBase + (uint32_t)(buf * (TN * BK * 2));
        #pragma unroll
        for (int ks = 0; ks < 4; ks++) {
            uint32_t a[4], b[4];
            int ach = ks * 2 + acsel;
            int bch = ks * 2 + bcsel;
            ldm4(a[0], a[1], a[2], a[3], aB + (uint32_t)((ach ^ axor) << 4));
            ldm4(b[0], b[1], b[2], b[3], bB + (uint32_t)((bch ^ bxor) << 4));
            mma_bf16(acc0, a, b[0], b[1]);
            mma_bf16(acc1, a, b[2], b[3]);
        }
        __syncthreads();
    }

    // ---- fused epilogue ----
    const float kgn = Kg[0] * (1.0f / (float)NN);
    const int tq = lane >> 2;        // fragment row within m8
    const int tr = lane & 3;         // fragment col pair
    __nv_bfloat16* __restrict__ Bn = g_scB[nxt];

    #pragma unroll
    for (int nb = 0; nb < 2; nb++) {
        const float* acc = nb ? acc1 : acc0;
        int n_even = n0 + wn * 16 + nb * 8 + tr * 2;   // even column = sin
        int b = n_even >> 1;
        #pragma unroll
        for (int half = 0; half < 2; half++) {
            int i = i0 + wm * 16 + half * 8 + tq;
            float S = acc[half * 2 + 0];
            float C = acc[half * 2 + 1];
            int idx = i * BB + b;
            float th = g_theta[idx];
            float si, ci;
            sincosf(th, &si, &ci);
            float coup = ci * S - si * C;
            float tn = th + DT * (omega[i] + kgn * coup);
            float s, c;
            sincosf(tn, &s, &c);
            g_theta[idx] = atan2f(s, c);               // wrap like reference
            Bn[(size_t)(2 * b) * NN + i]     = __float2bfloat16(s);
            Bn[(size_t)(2 * b + 1) * NN + i] = __float2bfloat16(c);
        }
    }
}

// ---------------------------------------------------------------------------
// finalize: theta -> out[0:B*N] (transposed), coherence -> out[B*N : +B]
// ---------------------------------------------------------------------------
__global__ void finalize_kernel(float* __restrict__ out) {
    int b = blockIdx.x;
    int t = threadIdx.x;
    __shared__ float rc[256], rs[256];

    float sumc = 0.f, sums = 0.f;
    for (int i = t; i < NN; i += 256) {
        float th = g_theta[i * BB + b];
        out[b * NN + i] = th;
        float s, c;
        sincosf(th, &s, &c);
        sums += s;
        sumc += c;
    }
    rc[t] = sumc; rs[t] = sums;
    __syncthreads();
    for (int off = 128; off > 0; off >>= 1) {
        if (t < off) { rc[t] += rc[t + off]; rs[t] += rs[t + off]; }
        __syncthreads();
    }
    if (t == 0) {
        float cm = rc[0] * (1.0f / (float)NN);
        float sm = rs[0] * (1.0f / (float)NN);
        out[BB * NN + b] = sqrtf(cm * cm + sm * sm);
    }
}

// ---------------------------------------------------------------------------
extern "C" void kernel_launch(void* const* d_in, const int* in_sizes, int n_in,
                              void* d_out, int out_size) {
    const float* theta_init = (const float*)d_in[0];
    const float* Kmat       = (const float*)d_in[1];
    const float* omega      = (const float*)d_in[2];
    const float* Kg         = (const float*)d_in[3];
    float* out = (float*)d_out;

    convK_kernel<<<NN * NN / 4 / 256, 256>>>(Kmat);
    init_theta_kernel<<<BB * NN / 256, 256>>>(theta_init);

    dim3 ggrid(NN / TM, NT / TN);   // (16, 8) = 128 CTAs
    for (int s = 0; s < STEPS; s++) {
        step_kernel<<<ggrid, 256>>>(omega, Kg, s & 1, (s + 1) & 1);
    }
    finalize_kernel<<<BB, 256>>>(out);
}